// round 14
// baseline (speedup 1.0000x reference)
#include <cuda_runtime.h>
#include <cstdint>

using u64t = unsigned long long;

constexpr int NT = 128;

// ---------------- shared-memory layout (floats) ----------------
constexpr int O_W000 = 0;      // 4096 (16,16,16)
constexpr int O_W110 = 4096;   // 1024
constexpr int O_W220 = 5120;   // 1024
constexpr int O_W011 = 6144;   // 1024
constexpr int O_W101 = 7168;   // 1024
constexpr int O_W121 = 8192;   // 512
constexpr int O_W211 = 8704;   // 512
constexpr int O_W022 = 9216;   // 1024
constexpr int O_W202 = 10240;  // 1024
constexpr int O_W112 = 11264;  // 512
constexpr int O_W222 = 11776;  // 512
// staging (lane-indexed, [feat][tid]): a1, a2 only
constexpr int O_SA1  = 12288;             // 24*NT = 3072
constexpr int O_SA2  = O_SA1 + 24*NT;     // 3072
constexpr int SMEM_FLOATS = O_SA2 + 24*NT; // 18432 floats = 73,728 B/CTA (3 CTAs = 216KB)

__device__ __forceinline__ u64t pk2(float lo, float hi) {
    u64t r; asm("mov.b64 %0,{%1,%2};" : "=l"(r) : "f"(lo), "f"(hi)); return r;
}
__device__ __forceinline__ u64t dup2(float v) { return pk2(v, v); }
__device__ __forceinline__ float2 up2(u64t p) {
    float2 t; asm("mov.b64 {%0,%1},%2;" : "=f"(t.x), "=f"(t.y) : "l"(p)); return t;
}
__device__ __forceinline__ u64t f2fma(u64t a, u64t b, u64t c) {
    u64t d; asm("fma.rn.f32x2 %0,%1,%2,%3;" : "=l"(d) : "l"(a), "l"(b), "l"(c)); return d;
}
__device__ __forceinline__ u64t f2mul(u64t a, u64t b) {
    u64t d; asm("mul.rn.f32x2 %0,%1,%2;" : "=l"(d) : "l"(a), "l"(b)); return d;
}
__device__ __forceinline__ float sigm(float v) {
    return 1.0f / (1.0f + __expf(-v));
}

// irrep-1 linear (weights via __ldg, scale folded into x): h -> regs, a(normact) -> staging
__device__ __forceinline__ void lin1(const float* __restrict__ xs,
                                     const float* __restrict__ lh,
                                     const float* __restrict__ la,
                                     float* __restrict__ smA, int tid,
                                     float* __restrict__ hv)
{
    const float lin8 = 0.35355339059327379f;
    float xv[24];
    #pragma unroll
    for (int q = 0; q < 6; q++) {
        float4 t = __ldg((const float4*)xs + q);
        xv[4*q+0]=t.x*lin8; xv[4*q+1]=t.y*lin8; xv[4*q+2]=t.z*lin8; xv[4*q+3]=t.w*lin8;
    }
    u64t hp[12], ap[12];
    #pragma unroll
    for (int j = 0; j < 12; j++) { hp[j]=0ull; ap[j]=0ull; }
    #pragma unroll
    for (int u = 0; u < 8; u++) {
        const u64t x0 = dup2(xv[u*3+0]), x1 = dup2(xv[u*3+1]), x2 = dup2(xv[u*3+2]);
        #pragma unroll
        for (int v2 = 0; v2 < 4; v2++) {
            const u64t wh = __ldg((const u64t*)(lh + u*8 + 2*v2));
            const u64t wa = __ldg((const u64t*)(la + u*8 + 2*v2));
            hp[v2*3+0] = f2fma(x0, wh, hp[v2*3+0]);
            hp[v2*3+1] = f2fma(x1, wh, hp[v2*3+1]);
            hp[v2*3+2] = f2fma(x2, wh, hp[v2*3+2]);
            ap[v2*3+0] = f2fma(x0, wa, ap[v2*3+0]);
            ap[v2*3+1] = f2fma(x1, wa, ap[v2*3+1]);
            ap[v2*3+2] = f2fma(x2, wa, ap[v2*3+2]);
        }
    }
    #pragma unroll
    for (int v2 = 0; v2 < 4; v2++) {
        float2 h_0 = up2(hp[v2*3+0]), h_1 = up2(hp[v2*3+1]), h_2 = up2(hp[v2*3+2]);
        float2 a_0 = up2(ap[v2*3+0]), a_1 = up2(ap[v2*3+1]), a_2 = up2(ap[v2*3+2]);
        {
            const int v = 2*v2;
            hv[v*3+0]=h_0.x; hv[v*3+1]=h_1.x; hv[v*3+2]=h_2.x;
            const float nrm = sqrtf(a_0.x*a_0.x + a_1.x*a_1.x + a_2.x*a_2.x);
            const float f = sigm(nrm) / ((nrm == 0.f) ? 1.f : nrm);
            smA[(v*3+0)*NT+tid]=a_0.x*f; smA[(v*3+1)*NT+tid]=a_1.x*f; smA[(v*3+2)*NT+tid]=a_2.x*f;
        }
        {
            const int v = 2*v2+1;
            hv[v*3+0]=h_0.y; hv[v*3+1]=h_1.y; hv[v*3+2]=h_2.y;
            const float nrm = sqrtf(a_0.y*a_0.y + a_1.y*a_1.y + a_2.y*a_2.y);
            const float f = sigm(nrm) / ((nrm == 0.f) ? 1.f : nrm);
            smA[(v*3+0)*NT+tid]=a_0.y*f; smA[(v*3+1)*NT+tid]=a_1.y*f; smA[(v*3+2)*NT+tid]=a_2.y*f;
        }
    }
}

// dot path: o0 += W[u,v,:16] * dot(hv_u, av_v), packed over w (both operands in regs)
__device__ __forceinline__ void dot_apply(const float* __restrict__ hv,
                                          const float* __restrict__ av,
                                          const float* __restrict__ wbase,
                                          u64t* __restrict__ o0)
{
    #pragma unroll
    for (int u = 0; u < 8; u++) {
        const float hx = hv[u*3], hy = hv[u*3+1], hz = hv[u*3+2];
        #pragma unroll
        for (int v = 0; v < 8; v++) {
            const float d = hx*av[v*3] + hy*av[v*3+1] + hz*av[v*3+2];
            const u64t d2 = dup2(d);
            const ulonglong2* wp = (const ulonglong2*)(wbase + (u*8 + v)*16);
            const ulonglong2 ta = wp[0], tb = wp[1];
            o0[0]=f2fma(d2,ta.x,o0[0]); o0[1]=f2fma(d2,ta.y,o0[1]);
            o0[2]=f2fma(d2,tb.x,o0[2]); o0[3]=f2fma(d2,tb.y,o0[3]);
            const ulonglong2 tc = wp[2], td = wp[3];
            o0[4]=f2fma(d2,tc.x,o0[4]); o0[5]=f2fma(d2,tc.y,o0[5]);
            o0[6]=f2fma(d2,td.x,o0[6]); o0[7]=f2fma(d2,td.y,o0[7]);
        }
    }
}

// cross path: o[w2*3+c] += Wp[u,v,:8] * cross(hv_u, av_v)[c]
__device__ __forceinline__ void cross_apply(const float* __restrict__ hv,
                                            const float* __restrict__ av,
                                            const float* __restrict__ wbase,
                                            u64t* __restrict__ o)
{
    #pragma unroll
    for (int u = 0; u < 8; u++) {
        const float ax = hv[u*3], ay = hv[u*3+1], az = hv[u*3+2];
        #pragma unroll
        for (int v = 0; v < 8; v++) {
            const float bx = av[v*3], by = av[v*3+1], bz = av[v*3+2];
            const u64t cx = dup2(ay*bz - az*by);
            const u64t cy = dup2(az*bx - ax*bz);
            const u64t cz = dup2(ax*by - ay*bx);
            const ulonglong2* wp = (const ulonglong2*)(wbase + (u*8+v)*8);
            const ulonglong2 ta = wp[0], tb = wp[1];
            const u64t wv[4] = {ta.x, ta.y, tb.x, tb.y};
            #pragma unroll
            for (int w2 = 0; w2 < 4; w2++) {
                o[w2*3+0] = f2fma(cx, wv[w2], o[w2*3+0]);
                o[w2*3+1] = f2fma(cy, wv[w2], o[w2*3+1]);
                o[w2*3+2] = f2fma(cz, wv[w2], o[w2*3+2]);
            }
        }
    }
}

// (0,l,l): M[v,w] = sum_u s16[u]*W[u,v,w]; o += a_v (x) M  (a from staging, per-v reads)
__device__ __forceinline__ void mpathA(const float* __restrict__ s16,
                                       const float* __restrict__ smA, int tid,
                                       const float* __restrict__ wbase,
                                       u64t* __restrict__ o)
{
    #pragma unroll
    for (int vc = 0; vc < 2; vc++) {
        u64t Mc[16];
        #pragma unroll
        for (int j = 0; j < 16; j++) Mc[j] = 0ull;
        #pragma unroll
        for (int u = 0; u < 16; u++) {
            const u64t hu2 = dup2(s16[u]);
            const ulonglong2* wp = (const ulonglong2*)(wbase + u*64 + vc*32);
            #pragma unroll
            for (int j = 0; j < 8; j++) {
                const ulonglong2 t = wp[j];
                Mc[2*j+0] = f2fma(hu2, t.x, Mc[2*j+0]);
                Mc[2*j+1] = f2fma(hu2, t.y, Mc[2*j+1]);
            }
        }
        #pragma unroll
        for (int vl = 0; vl < 4; vl++) {
            const int v = vc*4 + vl;
            const u64t b0 = dup2(smA[(v*3+0)*NT + tid]);
            const u64t b1 = dup2(smA[(v*3+1)*NT + tid]);
            const u64t b2 = dup2(smA[(v*3+2)*NT + tid]);
            #pragma unroll
            for (int w2 = 0; w2 < 4; w2++) {
                const u64t m = Mc[vl*4 + w2];
                o[w2*3+0] = f2fma(b0, m, o[w2*3+0]);
                o[w2*3+1] = f2fma(b1, m, o[w2*3+1]);
                o[w2*3+2] = f2fma(b2, m, o[w2*3+2]);
            }
        }
    }
}

// (l,0,l): M[u,w] = sum_v s16[v]*W[u,v,w]; o += h_u (x) M  (h in regs)
__device__ __forceinline__ void mpathB(const float* __restrict__ s16,
                                       const float* __restrict__ hv,
                                       const float* __restrict__ wbase,
                                       u64t* __restrict__ o)
{
    #pragma unroll
    for (int uc = 0; uc < 2; uc++) {
        u64t Mc[16];
        #pragma unroll
        for (int j = 0; j < 16; j++) Mc[j] = 0ull;
        #pragma unroll
        for (int v = 0; v < 16; v++) {
            const u64t av2 = dup2(s16[v]);
            #pragma unroll
            for (int ul = 0; ul < 4; ul++) {
                const int u = uc*4 + ul;
                const ulonglong2* wp = (const ulonglong2*)(wbase + u*128 + v*8);
                const ulonglong2 ta = wp[0], tb = wp[1];
                Mc[ul*4+0] = f2fma(av2, ta.x, Mc[ul*4+0]);
                Mc[ul*4+1] = f2fma(av2, ta.y, Mc[ul*4+1]);
                Mc[ul*4+2] = f2fma(av2, tb.x, Mc[ul*4+2]);
                Mc[ul*4+3] = f2fma(av2, tb.y, Mc[ul*4+3]);
            }
        }
        #pragma unroll
        for (int ul = 0; ul < 4; ul++) {
            const int u = uc*4 + ul;
            const u64t b0 = dup2(hv[u*3+0]);
            const u64t b1 = dup2(hv[u*3+1]);
            const u64t b2 = dup2(hv[u*3+2]);
            #pragma unroll
            for (int w2 = 0; w2 < 4; w2++) {
                const u64t m = Mc[ul*4 + w2];
                o[w2*3+0] = f2fma(b0, m, o[w2*3+0]);
                o[w2*3+1] = f2fma(b1, m, o[w2*3+1]);
                o[w2*3+2] = f2fma(b2, m, o[w2*3+2]);
            }
        }
    }
}

__global__ void __launch_bounds__(NT, 3)
e3nn_bal_kernel(const float* __restrict__ x,
                const float* __restrict__ l0h, const float* __restrict__ l1h, const float* __restrict__ l2h,
                const float* __restrict__ l0a, const float* __restrict__ l1a, const float* __restrict__ l2a,
                const float* __restrict__ w000, const float* __restrict__ w110, const float* __restrict__ w220,
                const float* __restrict__ w011, const float* __restrict__ w101, const float* __restrict__ w121,
                const float* __restrict__ w211, const float* __restrict__ w022, const float* __restrict__ w202,
                const float* __restrict__ w112, const float* __restrict__ w222,
                float* __restrict__ out, int rows)
{
    extern __shared__ float sm[];
    const int tid = threadIdx.x;

    const float s0   = 0.051031036307982884f;   // sqrt(1/384)
    const float s1   = 0.088388347648318447f;   // sqrt(3/384)
    const float i3   = 0.57735026918962576f;
    const float i6   = 0.40824829046386302f;
    const float c110 = s0 * i3;
    const float c1_3 = s1 * i3;
    const float c1_6 = s1 * i6;

    for (int i = tid; i < 4096; i += NT)
        sm[O_W000 + i] = w000[i] * s0;
    for (int i = tid; i < 1024; i += NT) {
        sm[O_W110 + i] = w110[i] * c110;
        sm[O_W220 + i] = w220[i] * c110;
        sm[O_W011 + i] = w011[i] * c1_3;
        sm[O_W101 + i] = w101[i] * c1_3;
        sm[O_W022 + i] = w022[i] * c1_3;
        sm[O_W202 + i] = w202[i] * c1_3;
    }
    for (int i = tid; i < 512; i += NT) {
        sm[O_W121 + i] = w121[i] * c1_6;
        sm[O_W211 + i] = w211[i] * c1_6;
        sm[O_W112 + i] = w112[i] * c1_6;
        sm[O_W222 + i] = w222[i] * c1_6;
    }
    __syncthreads();

    const int stride = gridDim.x * NT;
    #pragma unroll 1
    for (int row = blockIdx.x * NT + tid; row < rows; row += stride) {
        const float* xr = x + (size_t)row * 64u;

        // ---- irrep-1 linears: h1,h2 -> regs; a1,a2(normact) -> staging ----
        float h1[24], h2[24];
        lin1(xr + 16, l1h, l1a, sm + O_SA1, tid, h1);
        lin1(xr + 40, l2h, l2a, sm + O_SA2, tid, h2);

        // ---- l=0 linear (weights via __ldg): h0, a0 (post-normact) regs ----
        float h0[16], a0[16];
        {
            float xv0[16];
            #pragma unroll
            for (int q = 0; q < 4; q++) {
                float4 t = __ldg(((const float4*)xr) + q);
                xv0[4*q+0]=t.x*0.25f; xv0[4*q+1]=t.y*0.25f; xv0[4*q+2]=t.z*0.25f; xv0[4*q+3]=t.w*0.25f;
            }
            u64t h0p[8], a0p[8];
            #pragma unroll
            for (int q = 0; q < 8; q++) { h0p[q]=0ull; a0p[q]=0ull; }
            #pragma unroll
            for (int u = 0; u < 16; u++) {
                const u64t xu2 = dup2(xv0[u]);
                const ulonglong2* wh = (const ulonglong2*)(l0h + u*16);
                const ulonglong2* wa = (const ulonglong2*)(l0a + u*16);
                #pragma unroll
                for (int j = 0; j < 4; j++) {
                    const ulonglong2 th = __ldg(wh + j);
                    h0p[2*j+0] = f2fma(xu2, th.x, h0p[2*j+0]);
                    h0p[2*j+1] = f2fma(xu2, th.y, h0p[2*j+1]);
                    const ulonglong2 ta = __ldg(wa + j);
                    a0p[2*j+0] = f2fma(xu2, ta.x, a0p[2*j+0]);
                    a0p[2*j+1] = f2fma(xu2, ta.y, a0p[2*j+1]);
                }
            }
            #pragma unroll
            for (int q = 0; q < 8; q++) {
                float2 th = up2(h0p[q]); h0[2*q] = th.x; h0[2*q+1] = th.y;
                float2 ta = up2(a0p[q]);
                { const float v = ta.x, nn = fabsf(v); a0[2*q]   = (nn==0.f)?0.f : v*sigm(nn)/nn; }
                { const float v = ta.y, nn = fabsf(v); a0[2*q+1] = (nn==0.f)?0.f : v*sigm(nn)/nn; }
            }
        }

        float* orow = out + (size_t)row * 64u;

        // ================= out0 =================
        {
            u64t o0[8];
            #pragma unroll
            for (int q = 0; q < 8; q++) o0[q] = 0ull;

            // path (0,0,0)
            #pragma unroll
            for (int vc = 0; vc < 2; vc++) {
                u64t a0d8[8];
                #pragma unroll
                for (int vl = 0; vl < 8; vl++) a0d8[vl] = dup2(a0[vc*8+vl]);
                #pragma unroll
                for (int u = 0; u < 16; u++) {
                    const u64t hu2 = dup2(h0[u]);
                    #pragma unroll
                    for (int vl = 0; vl < 8; vl++) {
                        const u64t p2 = f2mul(hu2, a0d8[vl]);
                        const ulonglong2* wp = (const ulonglong2*)(sm + O_W000 + (u*16 + vc*8 + vl)*16);
                        const ulonglong2 ta = wp[0], tb = wp[1];
                        o0[0]=f2fma(p2,ta.x,o0[0]); o0[1]=f2fma(p2,ta.y,o0[1]);
                        o0[2]=f2fma(p2,tb.x,o0[2]); o0[3]=f2fma(p2,tb.y,o0[3]);
                        const ulonglong2 tc = wp[2], td = wp[3];
                        o0[4]=f2fma(p2,tc.x,o0[4]); o0[5]=f2fma(p2,tc.y,o0[5]);
                        o0[6]=f2fma(p2,td.x,o0[6]); o0[7]=f2fma(p2,td.y,o0[7]);
                    }
                }
            }
            // path (1,1,0): h1 regs, a1 hoisted from staging
            {
                float a1r[24];
                #pragma unroll
                for (int f = 0; f < 24; f++) a1r[f] = sm[O_SA1 + f*NT + tid];
                dot_apply(h1, a1r, sm + O_W110, o0);
            }
            // path (2,2,0): h2 regs, a2 hoisted
            {
                float a2r[24];
                #pragma unroll
                for (int f = 0; f < 24; f++) a2r[f] = sm[O_SA2 + f*NT + tid];
                dot_apply(h2, a2r, sm + O_W220, o0);
            }
            ulonglong2* o4 = (ulonglong2*)orow;
            #pragma unroll
            for (int j = 0; j < 4; j++) {
                ulonglong2 t; t.x = o0[2*j]; t.y = o0[2*j+1];
                o4[j] = t;
            }
        }

        // ================= out1 =================
        {
            u64t o1[12];
            #pragma unroll
            for (int j = 0; j < 12; j++) o1[j] = 0ull;

            mpathA(h0, sm + O_SA1, tid, sm + O_W011, o1);   // (0,1,1)
            mpathB(a0, h1, sm + O_W101, o1);                // (1,0,1)
            {
                float a2r[24];
                #pragma unroll
                for (int f = 0; f < 24; f++) a2r[f] = sm[O_SA2 + f*NT + tid];
                cross_apply(h1, a2r, sm + O_W121, o1);      // (1,2,1)
            }
            {
                float a1r[24];
                #pragma unroll
                for (int f = 0; f < 24; f++) a1r[f] = sm[O_SA1 + f*NT + tid];
                cross_apply(h2, a1r, sm + O_W211, o1);      // (2,1,1)
            }

            float o1s[24];
            #pragma unroll
            for (int w2 = 0; w2 < 4; w2++) {
                #pragma unroll
                for (int i = 0; i < 3; i++) {
                    float2 t = up2(o1[w2*3+i]);
                    o1s[(2*w2+0)*3+i] = t.x;
                    o1s[(2*w2+1)*3+i] = t.y;
                }
            }
            float4* o4 = (float4*)(orow + 16);
            #pragma unroll
            for (int q = 0; q < 6; q++)
                o4[q] = make_float4(o1s[4*q], o1s[4*q+1], o1s[4*q+2], o1s[4*q+3]);
        }

        // ================= out2 =================
        {
            u64t o2[12];
            #pragma unroll
            for (int j = 0; j < 12; j++) o2[j] = 0ull;

            mpathA(h0, sm + O_SA2, tid, sm + O_W022, o2);   // (0,2,2)
            mpathB(a0, h2, sm + O_W202, o2);                // (2,0,2)
            {
                float a1r[24];
                #pragma unroll
                for (int f = 0; f < 24; f++) a1r[f] = sm[O_SA1 + f*NT + tid];
                cross_apply(h1, a1r, sm + O_W112, o2);      // (1,1,2)
            }
            {
                float a2r[24];
                #pragma unroll
                for (int f = 0; f < 24; f++) a2r[f] = sm[O_SA2 + f*NT + tid];
                cross_apply(h2, a2r, sm + O_W222, o2);      // (2,2,2)
            }

            float o2s[24];
            #pragma unroll
            for (int w2 = 0; w2 < 4; w2++) {
                #pragma unroll
                for (int i = 0; i < 3; i++) {
                    float2 t = up2(o2[w2*3+i]);
                    o2s[(2*w2+0)*3+i] = t.x;
                    o2s[(2*w2+1)*3+i] = t.y;
                }
            }
            float4* o4 = (float4*)(orow + 40);
            #pragma unroll
            for (int q = 0; q < 6; q++)
                o4[q] = make_float4(o2s[4*q], o2s[4*q+1], o2s[4*q+2], o2s[4*q+3]);
        }
    }
}

extern "C" void kernel_launch(void* const* d_in, const int* in_sizes, int n_in,
                              void* d_out, int out_size)
{
    const float* x    = (const float*)d_in[0];
    const float* l0h  = (const float*)d_in[1];
    const float* l1h  = (const float*)d_in[2];
    const float* l2h  = (const float*)d_in[3];
    const float* l0a  = (const float*)d_in[4];
    const float* l1a  = (const float*)d_in[5];
    const float* l2a  = (const float*)d_in[6];
    const float* w000 = (const float*)d_in[7];
    const float* w110 = (const float*)d_in[8];
    const float* w220 = (const float*)d_in[9];
    const float* w011 = (const float*)d_in[10];
    const float* w101 = (const float*)d_in[11];
    const float* w121 = (const float*)d_in[12];
    const float* w211 = (const float*)d_in[13];
    const float* w022 = (const float*)d_in[14];
    const float* w202 = (const float*)d_in[15];
    const float* w112 = (const float*)d_in[16];
    const float* w222 = (const float*)d_in[17];
    float* out = (float*)d_out;

    const int rows = in_sizes[0] / 64;
    const size_t smem_bytes = SMEM_FLOATS * sizeof(float);
    cudaFuncSetAttribute(e3nn_bal_kernel,
                         cudaFuncAttributeMaxDynamicSharedMemorySize,
                         (int)smem_bytes);

    // 2 rows per thread (grid-stride); 524288/128/2 = 2048 exactly
    int grid = (rows + 2*NT - 1) / (2*NT);
    e3nn_bal_kernel<<<grid, NT, smem_bytes>>>(
        x, l0h, l1h, l2h, l0a, l1a, l2a,
        w000, w110, w220, w011, w101, w121, w211, w022, w202, w112, w222,
        out, rows);
}

// round 15
// speedup vs baseline: 1.0009x; 1.0009x over previous
#include <cuda_runtime.h>
#include <cstdint>

using u64t = unsigned long long;

constexpr int NT = 128;

// ---------------- shared-memory layout (floats) ----------------
constexpr int O_W000 = 0;      // 4096 (16,16,16)
constexpr int O_W110 = 4096;   // 1024
constexpr int O_W220 = 5120;   // 1024
constexpr int O_W011 = 6144;   // 1024
constexpr int O_W101 = 7168;   // 1024
constexpr int O_W121 = 8192;   // 512
constexpr int O_W211 = 8704;   // 512
constexpr int O_W022 = 9216;   // 1024
constexpr int O_W202 = 10240;  // 1024
constexpr int O_W112 = 11264;  // 512
constexpr int O_W222 = 11776;  // 512
// staging (lane-indexed, [feat][tid]): a1, a2 only
constexpr int O_SA1  = 12288;             // 24*NT = 3072
constexpr int O_SA2  = O_SA1 + 24*NT;     // 3072
constexpr int SMEM_FLOATS = O_SA2 + 24*NT; // 18432 floats = 73,728 B/CTA (3 CTAs = 216KB)

__device__ __forceinline__ u64t pk2(float lo, float hi) {
    u64t r; asm("mov.b64 %0,{%1,%2};" : "=l"(r) : "f"(lo), "f"(hi)); return r;
}
__device__ __forceinline__ u64t dup2(float v) { return pk2(v, v); }
__device__ __forceinline__ float2 up2(u64t p) {
    float2 t; asm("mov.b64 {%0,%1},%2;" : "=f"(t.x), "=f"(t.y) : "l"(p)); return t;
}
__device__ __forceinline__ u64t f2fma(u64t a, u64t b, u64t c) {
    u64t d; asm("fma.rn.f32x2 %0,%1,%2,%3;" : "=l"(d) : "l"(a), "l"(b), "l"(c)); return d;
}
__device__ __forceinline__ u64t f2mul(u64t a, u64t b) {
    u64t d; asm("mul.rn.f32x2 %0,%1,%2;" : "=l"(d) : "l"(a), "l"(b)); return d;
}
__device__ __forceinline__ float sigm(float v) {
    return 1.0f / (1.0f + __expf(-v));
}

// irrep-1 linear (weights via __ldg, scale folded into x): h -> regs, a(normact) -> staging
__device__ __forceinline__ void lin1(const float* __restrict__ xs,
                                     const float* __restrict__ lh,
                                     const float* __restrict__ la,
                                     float* __restrict__ smA, int tid,
                                     float* __restrict__ hv)
{
    const float lin8 = 0.35355339059327379f;
    float xv[24];
    #pragma unroll
    for (int q = 0; q < 6; q++) {
        float4 t = __ldg((const float4*)xs + q);
        xv[4*q+0]=t.x*lin8; xv[4*q+1]=t.y*lin8; xv[4*q+2]=t.z*lin8; xv[4*q+3]=t.w*lin8;
    }
    u64t hp[12], ap[12];
    #pragma unroll
    for (int j = 0; j < 12; j++) { hp[j]=0ull; ap[j]=0ull; }
    #pragma unroll
    for (int u = 0; u < 8; u++) {
        const u64t x0 = dup2(xv[u*3+0]), x1 = dup2(xv[u*3+1]), x2 = dup2(xv[u*3+2]);
        #pragma unroll
        for (int v2 = 0; v2 < 4; v2++) {
            const u64t wh = __ldg((const u64t*)(lh + u*8 + 2*v2));
            const u64t wa = __ldg((const u64t*)(la + u*8 + 2*v2));
            hp[v2*3+0] = f2fma(x0, wh, hp[v2*3+0]);
            hp[v2*3+1] = f2fma(x1, wh, hp[v2*3+1]);
            hp[v2*3+2] = f2fma(x2, wh, hp[v2*3+2]);
            ap[v2*3+0] = f2fma(x0, wa, ap[v2*3+0]);
            ap[v2*3+1] = f2fma(x1, wa, ap[v2*3+1]);
            ap[v2*3+2] = f2fma(x2, wa, ap[v2*3+2]);
        }
    }
    #pragma unroll
    for (int v2 = 0; v2 < 4; v2++) {
        float2 h_0 = up2(hp[v2*3+0]), h_1 = up2(hp[v2*3+1]), h_2 = up2(hp[v2*3+2]);
        float2 a_0 = up2(ap[v2*3+0]), a_1 = up2(ap[v2*3+1]), a_2 = up2(ap[v2*3+2]);
        {
            const int v = 2*v2;
            hv[v*3+0]=h_0.x; hv[v*3+1]=h_1.x; hv[v*3+2]=h_2.x;
            const float nrm = sqrtf(a_0.x*a_0.x + a_1.x*a_1.x + a_2.x*a_2.x);
            const float f = sigm(nrm) / ((nrm == 0.f) ? 1.f : nrm);
            smA[(v*3+0)*NT+tid]=a_0.x*f; smA[(v*3+1)*NT+tid]=a_1.x*f; smA[(v*3+2)*NT+tid]=a_2.x*f;
        }
        {
            const int v = 2*v2+1;
            hv[v*3+0]=h_0.y; hv[v*3+1]=h_1.y; hv[v*3+2]=h_2.y;
            const float nrm = sqrtf(a_0.y*a_0.y + a_1.y*a_1.y + a_2.y*a_2.y);
            const float f = sigm(nrm) / ((nrm == 0.f) ? 1.f : nrm);
            smA[(v*3+0)*NT+tid]=a_0.y*f; smA[(v*3+1)*NT+tid]=a_1.y*f; smA[(v*3+2)*NT+tid]=a_2.y*f;
        }
    }
}

// dot path: o0 += W[u,v,:16] * dot(hv_u, av_v), packed over w (both operands in regs)
__device__ __forceinline__ void dot_apply(const float* __restrict__ hv,
                                          const float* __restrict__ av,
                                          const float* __restrict__ wbase,
                                          u64t* __restrict__ o0)
{
    #pragma unroll
    for (int u = 0; u < 8; u++) {
        const float hx = hv[u*3], hy = hv[u*3+1], hz = hv[u*3+2];
        #pragma unroll
        for (int v = 0; v < 8; v++) {
            const float d = hx*av[v*3] + hy*av[v*3+1] + hz*av[v*3+2];
            const u64t d2 = dup2(d);
            const ulonglong2* wp = (const ulonglong2*)(wbase + (u*8 + v)*16);
            const ulonglong2 ta = wp[0], tb = wp[1];
            o0[0]=f2fma(d2,ta.x,o0[0]); o0[1]=f2fma(d2,ta.y,o0[1]);
            o0[2]=f2fma(d2,tb.x,o0[2]); o0[3]=f2fma(d2,tb.y,o0[3]);
            const ulonglong2 tc = wp[2], td = wp[3];
            o0[4]=f2fma(d2,tc.x,o0[4]); o0[5]=f2fma(d2,tc.y,o0[5]);
            o0[6]=f2fma(d2,td.x,o0[6]); o0[7]=f2fma(d2,td.y,o0[7]);
        }
    }
}

// cross path: o[w2*3+c] += Wp[u,v,:8] * cross(hv_u, av_v)[c]
__device__ __forceinline__ void cross_apply(const float* __restrict__ hv,
                                            const float* __restrict__ av,
                                            const float* __restrict__ wbase,
                                            u64t* __restrict__ o)
{
    #pragma unroll
    for (int u = 0; u < 8; u++) {
        const float ax = hv[u*3], ay = hv[u*3+1], az = hv[u*3+2];
        #pragma unroll
        for (int v = 0; v < 8; v++) {
            const float bx = av[v*3], by = av[v*3+1], bz = av[v*3+2];
            const u64t cx = dup2(ay*bz - az*by);
            const u64t cy = dup2(az*bx - ax*bz);
            const u64t cz = dup2(ax*by - ay*bx);
            const ulonglong2* wp = (const ulonglong2*)(wbase + (u*8+v)*8);
            const ulonglong2 ta = wp[0], tb = wp[1];
            const u64t wv[4] = {ta.x, ta.y, tb.x, tb.y};
            #pragma unroll
            for (int w2 = 0; w2 < 4; w2++) {
                o[w2*3+0] = f2fma(cx, wv[w2], o[w2*3+0]);
                o[w2*3+1] = f2fma(cy, wv[w2], o[w2*3+1]);
                o[w2*3+2] = f2fma(cz, wv[w2], o[w2*3+2]);
            }
        }
    }
}

// (0,l,l): M[v,w] = sum_u s16[u]*W[u,v,w]; o += a_v (x) M  (a from staging, per-v reads)
__device__ __forceinline__ void mpathA(const float* __restrict__ s16,
                                       const float* __restrict__ smA, int tid,
                                       const float* __restrict__ wbase,
                                       u64t* __restrict__ o)
{
    #pragma unroll
    for (int vc = 0; vc < 2; vc++) {
        u64t Mc[16];
        #pragma unroll
        for (int j = 0; j < 16; j++) Mc[j] = 0ull;
        #pragma unroll
        for (int u = 0; u < 16; u++) {
            const u64t hu2 = dup2(s16[u]);
            const ulonglong2* wp = (const ulonglong2*)(wbase + u*64 + vc*32);
            #pragma unroll
            for (int j = 0; j < 8; j++) {
                const ulonglong2 t = wp[j];
                Mc[2*j+0] = f2fma(hu2, t.x, Mc[2*j+0]);
                Mc[2*j+1] = f2fma(hu2, t.y, Mc[2*j+1]);
            }
        }
        #pragma unroll
        for (int vl = 0; vl < 4; vl++) {
            const int v = vc*4 + vl;
            const u64t b0 = dup2(smA[(v*3+0)*NT + tid]);
            const u64t b1 = dup2(smA[(v*3+1)*NT + tid]);
            const u64t b2 = dup2(smA[(v*3+2)*NT + tid]);
            #pragma unroll
            for (int w2 = 0; w2 < 4; w2++) {
                const u64t m = Mc[vl*4 + w2];
                o[w2*3+0] = f2fma(b0, m, o[w2*3+0]);
                o[w2*3+1] = f2fma(b1, m, o[w2*3+1]);
                o[w2*3+2] = f2fma(b2, m, o[w2*3+2]);
            }
        }
    }
}

// (l,0,l): M[u,w] = sum_v s16[v]*W[u,v,w]; o += h_u (x) M  (h in regs)
__device__ __forceinline__ void mpathB(const float* __restrict__ s16,
                                       const float* __restrict__ hv,
                                       const float* __restrict__ wbase,
                                       u64t* __restrict__ o)
{
    #pragma unroll
    for (int uc = 0; uc < 2; uc++) {
        u64t Mc[16];
        #pragma unroll
        for (int j = 0; j < 16; j++) Mc[j] = 0ull;
        #pragma unroll
        for (int v = 0; v < 16; v++) {
            const u64t av2 = dup2(s16[v]);
            #pragma unroll
            for (int ul = 0; ul < 4; ul++) {
                const int u = uc*4 + ul;
                const ulonglong2* wp = (const ulonglong2*)(wbase + u*128 + v*8);
                const ulonglong2 ta = wp[0], tb = wp[1];
                Mc[ul*4+0] = f2fma(av2, ta.x, Mc[ul*4+0]);
                Mc[ul*4+1] = f2fma(av2, ta.y, Mc[ul*4+1]);
                Mc[ul*4+2] = f2fma(av2, tb.x, Mc[ul*4+2]);
                Mc[ul*4+3] = f2fma(av2, tb.y, Mc[ul*4+3]);
            }
        }
        #pragma unroll
        for (int ul = 0; ul < 4; ul++) {
            const int u = uc*4 + ul;
            const u64t b0 = dup2(hv[u*3+0]);
            const u64t b1 = dup2(hv[u*3+1]);
            const u64t b2 = dup2(hv[u*3+2]);
            #pragma unroll
            for (int w2 = 0; w2 < 4; w2++) {
                const u64t m = Mc[ul*4 + w2];
                o[w2*3+0] = f2fma(b0, m, o[w2*3+0]);
                o[w2*3+1] = f2fma(b1, m, o[w2*3+1]);
                o[w2*3+2] = f2fma(b2, m, o[w2*3+2]);
            }
        }
    }
}

__global__ void __launch_bounds__(NT, 3)
e3nn_bal_kernel(const float* __restrict__ x,
                const float* __restrict__ l0h, const float* __restrict__ l1h, const float* __restrict__ l2h,
                const float* __restrict__ l0a, const float* __restrict__ l1a, const float* __restrict__ l2a,
                const float* __restrict__ w000, const float* __restrict__ w110, const float* __restrict__ w220,
                const float* __restrict__ w011, const float* __restrict__ w101, const float* __restrict__ w121,
                const float* __restrict__ w211, const float* __restrict__ w022, const float* __restrict__ w202,
                const float* __restrict__ w112, const float* __restrict__ w222,
                float* __restrict__ out, int rows)
{
    extern __shared__ float sm[];
    const int tid = threadIdx.x;

    const float s0   = 0.051031036307982884f;   // sqrt(1/384)
    const float s1   = 0.088388347648318447f;   // sqrt(3/384)
    const float i3   = 0.57735026918962576f;
    const float i6   = 0.40824829046386302f;
    const float c110 = s0 * i3;
    const float c1_3 = s1 * i3;
    const float c1_6 = s1 * i6;

    for (int i = tid; i < 4096; i += NT)
        sm[O_W000 + i] = w000[i] * s0;
    for (int i = tid; i < 1024; i += NT) {
        sm[O_W110 + i] = w110[i] * c110;
        sm[O_W220 + i] = w220[i] * c110;
        sm[O_W011 + i] = w011[i] * c1_3;
        sm[O_W101 + i] = w101[i] * c1_3;
        sm[O_W022 + i] = w022[i] * c1_3;
        sm[O_W202 + i] = w202[i] * c1_3;
    }
    for (int i = tid; i < 512; i += NT) {
        sm[O_W121 + i] = w121[i] * c1_6;
        sm[O_W211 + i] = w211[i] * c1_6;
        sm[O_W112 + i] = w112[i] * c1_6;
        sm[O_W222 + i] = w222[i] * c1_6;
    }
    __syncthreads();

    const int stride = gridDim.x * NT;
    #pragma unroll 1
    for (int row = blockIdx.x * NT + tid; row < rows; row += stride) {
        const float* xr = x + (size_t)row * 64u;

        // ---- irrep-1 linears: h1,h2 -> regs; a1,a2(normact) -> staging ----
        float h1[24], h2[24];
        lin1(xr + 16, l1h, l1a, sm + O_SA1, tid, h1);
        lin1(xr + 40, l2h, l2a, sm + O_SA2, tid, h2);

        // ---- l=0 linear (weights via __ldg): h0, a0 (post-normact) regs ----
        float h0[16], a0[16];
        {
            float xv0[16];
            #pragma unroll
            for (int q = 0; q < 4; q++) {
                float4 t = __ldg(((const float4*)xr) + q);
                xv0[4*q+0]=t.x*0.25f; xv0[4*q+1]=t.y*0.25f; xv0[4*q+2]=t.z*0.25f; xv0[4*q+3]=t.w*0.25f;
            }
            u64t h0p[8], a0p[8];
            #pragma unroll
            for (int q = 0; q < 8; q++) { h0p[q]=0ull; a0p[q]=0ull; }
            #pragma unroll
            for (int u = 0; u < 16; u++) {
                const u64t xu2 = dup2(xv0[u]);
                const ulonglong2* wh = (const ulonglong2*)(l0h + u*16);
                const ulonglong2* wa = (const ulonglong2*)(l0a + u*16);
                #pragma unroll
                for (int j = 0; j < 4; j++) {
                    const ulonglong2 th = __ldg(wh + j);
                    h0p[2*j+0] = f2fma(xu2, th.x, h0p[2*j+0]);
                    h0p[2*j+1] = f2fma(xu2, th.y, h0p[2*j+1]);
                    const ulonglong2 ta = __ldg(wa + j);
                    a0p[2*j+0] = f2fma(xu2, ta.x, a0p[2*j+0]);
                    a0p[2*j+1] = f2fma(xu2, ta.y, a0p[2*j+1]);
                }
            }
            #pragma unroll
            for (int q = 0; q < 8; q++) {
                float2 th = up2(h0p[q]); h0[2*q] = th.x; h0[2*q+1] = th.y;
                float2 ta = up2(a0p[q]);
                { const float v = ta.x, nn = fabsf(v); a0[2*q]   = (nn==0.f)?0.f : v*sigm(nn)/nn; }
                { const float v = ta.y, nn = fabsf(v); a0[2*q+1] = (nn==0.f)?0.f : v*sigm(nn)/nn; }
            }
        }

        float* orow = out + (size_t)row * 64u;

        // ================= out0 =================
        {
            u64t o0[8];
            #pragma unroll
            for (int q = 0; q < 8; q++) o0[q] = 0ull;

            // path (0,0,0)
            #pragma unroll
            for (int vc = 0; vc < 2; vc++) {
                u64t a0d8[8];
                #pragma unroll
                for (int vl = 0; vl < 8; vl++) a0d8[vl] = dup2(a0[vc*8+vl]);
                #pragma unroll
                for (int u = 0; u < 16; u++) {
                    const u64t hu2 = dup2(h0[u]);
                    #pragma unroll
                    for (int vl = 0; vl < 8; vl++) {
                        const u64t p2 = f2mul(hu2, a0d8[vl]);
                        const ulonglong2* wp = (const ulonglong2*)(sm + O_W000 + (u*16 + vc*8 + vl)*16);
                        const ulonglong2 ta = wp[0], tb = wp[1];
                        o0[0]=f2fma(p2,ta.x,o0[0]); o0[1]=f2fma(p2,ta.y,o0[1]);
                        o0[2]=f2fma(p2,tb.x,o0[2]); o0[3]=f2fma(p2,tb.y,o0[3]);
                        const ulonglong2 tc = wp[2], td = wp[3];
                        o0[4]=f2fma(p2,tc.x,o0[4]); o0[5]=f2fma(p2,tc.y,o0[5]);
                        o0[6]=f2fma(p2,td.x,o0[6]); o0[7]=f2fma(p2,td.y,o0[7]);
                    }
                }
            }
            // path (1,1,0): h1 regs, a1 hoisted from staging
            {
                float a1r[24];
                #pragma unroll
                for (int f = 0; f < 24; f++) a1r[f] = sm[O_SA1 + f*NT + tid];
                dot_apply(h1, a1r, sm + O_W110, o0);
            }
            // path (2,2,0): h2 regs, a2 hoisted
            {
                float a2r[24];
                #pragma unroll
                for (int f = 0; f < 24; f++) a2r[f] = sm[O_SA2 + f*NT + tid];
                dot_apply(h2, a2r, sm + O_W220, o0);
            }
            ulonglong2* o4 = (ulonglong2*)orow;
            #pragma unroll
            for (int j = 0; j < 4; j++) {
                ulonglong2 t; t.x = o0[2*j]; t.y = o0[2*j+1];
                o4[j] = t;
            }
        }

        // ================= out1 =================
        {
            u64t o1[12];
            #pragma unroll
            for (int j = 0; j < 12; j++) o1[j] = 0ull;

            mpathA(h0, sm + O_SA1, tid, sm + O_W011, o1);   // (0,1,1)
            mpathB(a0, h1, sm + O_W101, o1);                // (1,0,1)
            {
                float a2r[24];
                #pragma unroll
                for (int f = 0; f < 24; f++) a2r[f] = sm[O_SA2 + f*NT + tid];
                cross_apply(h1, a2r, sm + O_W121, o1);      // (1,2,1)
            }
            {
                float a1r[24];
                #pragma unroll
                for (int f = 0; f < 24; f++) a1r[f] = sm[O_SA1 + f*NT + tid];
                cross_apply(h2, a1r, sm + O_W211, o1);      // (2,1,1)
            }

            float o1s[24];
            #pragma unroll
            for (int w2 = 0; w2 < 4; w2++) {
                #pragma unroll
                for (int i = 0; i < 3; i++) {
                    float2 t = up2(o1[w2*3+i]);
                    o1s[(2*w2+0)*3+i] = t.x;
                    o1s[(2*w2+1)*3+i] = t.y;
                }
            }
            float4* o4 = (float4*)(orow + 16);
            #pragma unroll
            for (int q = 0; q < 6; q++)
                o4[q] = make_float4(o1s[4*q], o1s[4*q+1], o1s[4*q+2], o1s[4*q+3]);
        }

        // ================= out2 =================
        {
            u64t o2[12];
            #pragma unroll
            for (int j = 0; j < 12; j++) o2[j] = 0ull;

            mpathA(h0, sm + O_SA2, tid, sm + O_W022, o2);   // (0,2,2)
            mpathB(a0, h2, sm + O_W202, o2);                // (2,0,2)
            {
                float a1r[24];
                #pragma unroll
                for (int f = 0; f < 24; f++) a1r[f] = sm[O_SA1 + f*NT + tid];
                cross_apply(h1, a1r, sm + O_W112, o2);      // (1,1,2)
            }
            {
                float a2r[24];
                #pragma unroll
                for (int f = 0; f < 24; f++) a2r[f] = sm[O_SA2 + f*NT + tid];
                cross_apply(h2, a2r, sm + O_W222, o2);      // (2,2,2)
            }

            float o2s[24];
            #pragma unroll
            for (int w2 = 0; w2 < 4; w2++) {
                #pragma unroll
                for (int i = 0; i < 3; i++) {
                    float2 t = up2(o2[w2*3+i]);
                    o2s[(2*w2+0)*3+i] = t.x;
                    o2s[(2*w2+1)*3+i] = t.y;
                }
            }
            float4* o4 = (float4*)(orow + 40);
            #pragma unroll
            for (int q = 0; q < 6; q++)
                o4[q] = make_float4(o2s[4*q], o2s[4*q+1], o2s[4*q+2], o2s[4*q+3]);
        }
    }
}

extern "C" void kernel_launch(void* const* d_in, const int* in_sizes, int n_in,
                              void* d_out, int out_size)
{
    const float* x    = (const float*)d_in[0];
    const float* l0h  = (const float*)d_in[1];
    const float* l1h  = (const float*)d_in[2];
    const float* l2h  = (const float*)d_in[3];
    const float* l0a  = (const float*)d_in[4];
    const float* l1a  = (const float*)d_in[5];
    const float* l2a  = (const float*)d_in[6];
    const float* w000 = (const float*)d_in[7];
    const float* w110 = (const float*)d_in[8];
    const float* w220 = (const float*)d_in[9];
    const float* w011 = (const float*)d_in[10];
    const float* w101 = (const float*)d_in[11];
    const float* w121 = (const float*)d_in[12];
    const float* w211 = (const float*)d_in[13];
    const float* w022 = (const float*)d_in[14];
    const float* w202 = (const float*)d_in[15];
    const float* w112 = (const float*)d_in[16];
    const float* w222 = (const float*)d_in[17];
    float* out = (float*)d_out;

    const int rows = in_sizes[0] / 64;
    const size_t smem_bytes = SMEM_FLOATS * sizeof(float);
    cudaFuncSetAttribute(e3nn_bal_kernel,
                         cudaFuncAttributeMaxDynamicSharedMemorySize,
                         (int)smem_bytes);

    // 2 rows per thread (grid-stride); 524288/128/2 = 2048 exactly
    int grid = (rows + 2*NT - 1) / (2*NT);
    e3nn_bal_kernel<<<grid, NT, smem_bytes>>>(
        x, l0h, l1h, l2h, l0a, l1a, l2a,
        w000, w110, w220, w011, w101, w121, w211, w022, w202, w112, w222,
        out, rows);
}